// round 2
// baseline (speedup 1.0000x reference)
#include <cuda_runtime.h>
#include <math.h>

// Problem constants
constexpr int B  = 2;
constexpr int L  = 2048;
constexpr int D  = 1024;
constexpr int H  = 16;
constexpr int DH = 64;
constexpr int BL = B * L;          // 4096 tokens
constexpr float EPS   = 1e-5f;
constexpr float SCALE = 0.125f;    // 1/sqrt(64)
constexpr float LOG_ROPE_BASE = 9.210340371976184f; // ln(10000)

typedef unsigned long long u64;

// ---------------------------------------------------------------------------
// Packed fp32x2 helpers (Blackwell FFMA2 — exact fp32 semantics, 2x lanes)
// ---------------------------------------------------------------------------
__device__ __forceinline__ u64 f2_pack(float lo, float hi) {
    u64 r; asm("mov.b64 %0, {%1, %2};" : "=l"(r) : "f"(lo), "f"(hi)); return r;
}
__device__ __forceinline__ u64 f2_dup(float v) { return f2_pack(v, v); }
__device__ __forceinline__ u64 f2_fma(u64 a, u64 b, u64 c) {
    u64 d; asm("fma.rn.f32x2 %0, %1, %2, %3;" : "=l"(d) : "l"(a), "l"(b), "l"(c)); return d;
}
__device__ __forceinline__ u64 f2_mul(u64 a, u64 b) {
    u64 d; asm("mul.rn.f32x2 %0, %1, %2;" : "=l"(d) : "l"(a), "l"(b)); return d;
}
__device__ __forceinline__ float2 f2_unpack(u64 v) {
    float2 r; asm("mov.b64 {%0, %1}, %2;" : "=f"(r.x), "=f"(r.y) : "l"(v)); return r;
}

// ---------------------------------------------------------------------------
// Scratch (static device memory; no runtime allocation)
// ---------------------------------------------------------------------------
__device__ float g_h[BL * D];            // post-LN hidden
__device__ float g_qkv[BL * 3 * D];      // qkv projection
__device__ float g_q[B * H * L * DH];    // q  [B,H,L,DH]
__device__ float g_k[B * H * L * DH];    // k  [B,H,L,DH]
__device__ float g_v[B * H * L * DH];    // v  [B,H,L,DH]
__device__ float g_ctx[BL * D];          // attention output [B,L,H*DH]

// ---------------------------------------------------------------------------
// Block reduction (256 threads)
// ---------------------------------------------------------------------------
__device__ __forceinline__ float block_reduce_sum_256(float v, float* sbuf) {
    int tid = threadIdx.x;
    #pragma unroll
    for (int o = 16; o > 0; o >>= 1) v += __shfl_xor_sync(0xffffffffu, v, o);
    if ((tid & 31) == 0) sbuf[tid >> 5] = v;
    __syncthreads();
    if (tid < 8) {
        float w = sbuf[tid];
        #pragma unroll
        for (int o = 4; o > 0; o >>= 1) w += __shfl_xor_sync(0xffu, w, o);
        if (tid == 0) sbuf[0] = w;
    }
    __syncthreads();
    float r = sbuf[0];
    __syncthreads();
    return r;
}

// ---------------------------------------------------------------------------
// Kernel 1: LayerNorm over D=1024, one block (256 thr) per token.
// ---------------------------------------------------------------------------
__global__ void __launch_bounds__(256) ln_kernel(
    const float* __restrict__ x,
    const float* __restrict__ w,
    const float* __restrict__ bias)
{
    __shared__ float sbuf[8];
    const int t   = blockIdx.x;
    const int tid = threadIdx.x;

    const float4 xv = *(const float4*)(x + (size_t)t * D + 4 * tid);
    float s  = xv.x + xv.y + xv.z + xv.w;
    float ss = fmaf(xv.x, xv.x, fmaf(xv.y, xv.y, fmaf(xv.z, xv.z, xv.w * xv.w)));
    s  = block_reduce_sum_256(s,  sbuf);
    ss = block_reduce_sum_256(ss, sbuf);

    const float mu = s * (1.0f / D);
    const float rs = rsqrtf(ss * (1.0f / D) - mu * mu + EPS);

    const float4 wv = *(const float4*)(w    + 4 * tid);
    const float4 bv = *(const float4*)(bias + 4 * tid);
    float4 ov;
    ov.x = (xv.x - mu) * rs * wv.x + bv.x;
    ov.y = (xv.y - mu) * rs * wv.y + bv.y;
    ov.z = (xv.z - mu) * rs * wv.z + bv.z;
    ov.w = (xv.w - mu) * rs * wv.w + bv.w;
    *(float4*)(g_h + (size_t)t * D + 4 * tid) = ov;
}

// ---------------------------------------------------------------------------
// Kernel 2/5: SGEMM-NT  C[m,n] = sum_k A[m,k] * Bm[n,k]
// 128x128x16 tile, 256 threads, 8x8 fragment per thread, FFMA2 inner loop.
// ---------------------------------------------------------------------------
constexpr int GBM = 128, GBN = 128, GBK = 16;

__global__ void __launch_bounds__(256) gemm_nt_kernel(
    const float* __restrict__ A,
    const float* __restrict__ Bm,
    float* __restrict__ C,
    int M, int N, int K)
{
    __shared__ float As[GBK][GBM];
    __shared__ float Bs[GBK][GBN];

    const int tid = threadIdx.x;
    const int tx  = tid & 15;
    const int ty  = tid >> 4;
    const int m0  = blockIdx.y * GBM;
    const int n0  = blockIdx.x * GBN;

    u64 acc2[8][4];
    #pragma unroll
    for (int i = 0; i < 8; i++)
        #pragma unroll
        for (int j = 0; j < 4; j++) acc2[i][j] = 0ull;

    for (int k0 = 0; k0 < K; k0 += GBK) {
        #pragma unroll
        for (int r = 0; r < 2; r++) {
            int idx  = tid + r * 256;           // 0..511 float4 slots
            int row  = idx >> 2;                // 0..127
            int colb = (idx & 3) * 4;           // 0,4,8,12
            float4 av = *(const float4*)(A  + (size_t)(m0 + row) * K + k0 + colb);
            float4 bv = *(const float4*)(Bm + (size_t)(n0 + row) * K + k0 + colb);
            As[colb + 0][row] = av.x; As[colb + 1][row] = av.y;
            As[colb + 2][row] = av.z; As[colb + 3][row] = av.w;
            Bs[colb + 0][row] = bv.x; Bs[colb + 1][row] = bv.y;
            Bs[colb + 2][row] = bv.z; Bs[colb + 3][row] = bv.w;
        }
        __syncthreads();

        #pragma unroll
        for (int kk = 0; kk < GBK; kk++) {
            float af[8];
            *(float4*)&af[0] = *(const float4*)&As[kk][ty * 8];
            *(float4*)&af[4] = *(const float4*)&As[kk][ty * 8 + 4];
            ulonglong2 tb0 = *(const ulonglong2*)&Bs[kk][tx * 8];
            ulonglong2 tb1 = *(const ulonglong2*)&Bs[kk][tx * 8 + 4];
            u64 b2[4] = {tb0.x, tb0.y, tb1.x, tb1.y};
            #pragma unroll
            for (int i = 0; i < 8; i++) {
                u64 ad = f2_dup(af[i]);
                #pragma unroll
                for (int j = 0; j < 4; j++)
                    acc2[i][j] = f2_fma(ad, b2[j], acc2[i][j]);
            }
        }
        __syncthreads();
    }

    #pragma unroll
    for (int i = 0; i < 8; i++) {
        float* cr = C + (size_t)(m0 + ty * 8 + i) * N + n0 + tx * 8;
        float2 c0 = f2_unpack(acc2[i][0]);
        float2 c1 = f2_unpack(acc2[i][1]);
        float2 c2 = f2_unpack(acc2[i][2]);
        float2 c3 = f2_unpack(acc2[i][3]);
        *(float4*)(cr)     = make_float4(c0.x, c0.y, c1.x, c1.y);
        *(float4*)(cr + 4) = make_float4(c2.x, c2.y, c3.x, c3.y);
    }
}

// ---------------------------------------------------------------------------
// Kernel 3: per-token weight-only LN on q/k + RoPE + transpose into [B,H,L,DH]
// ---------------------------------------------------------------------------
__global__ void __launch_bounds__(256) qk_rope_kernel(
    const float* __restrict__ q_ln_w,
    const float* __restrict__ k_ln_w)
{
    __shared__ float sm[D];
    __shared__ float sbuf[8];

    const int t   = blockIdx.x;
    const int tid = threadIdx.x;
    const int b   = t / L;
    const int l   = t % L;

    #pragma unroll
    for (int seg = 0; seg < 2; seg++) {
        const float* base = g_qkv + (size_t)t * (3 * D) + seg * D;
        const float* w    = (seg == 0) ? q_ln_w : k_ln_w;
        float*       dst  = (seg == 0) ? g_q    : g_k;

        const float4 xv = *(const float4*)(base + 4 * tid);
        float s  = xv.x + xv.y + xv.z + xv.w;
        float ss = fmaf(xv.x, xv.x, fmaf(xv.y, xv.y, fmaf(xv.z, xv.z, xv.w * xv.w)));
        s  = block_reduce_sum_256(s,  sbuf);
        ss = block_reduce_sum_256(ss, sbuf);
        const float mu = s * (1.0f / D);
        const float rs = rsqrtf(ss * (1.0f / D) - mu * mu + EPS);

        const float4 wv = *(const float4*)(w + 4 * tid);
        sm[4 * tid + 0] = (xv.x - mu) * rs * wv.x;
        sm[4 * tid + 1] = (xv.y - mu) * rs * wv.y;
        sm[4 * tid + 2] = (xv.z - mu) * rs * wv.z;
        sm[4 * tid + 3] = (xv.w - mu) * rs * wv.w;
        __syncthreads();

        float out[4];
        #pragma unroll
        for (int c = 0; c < 4; c++) {
            int d  = 4 * tid + c;
            int dh = d & 63;
            int i  = dh & 31;
            float inv_freq = expf(-(float)(2 * i) * (1.0f / 64.0f) * LOG_ROPE_BASE);
            float freq = (float)l * inv_freq;
            float sn, cs;
            sincosf(freq, &sn, &cs);
            if (dh < 32) out[c] = sm[d] * cs - sm[d + 32] * sn;
            else         out[c] = sm[d] * cs + sm[d - 32] * sn;
        }
        const int d0   = 4 * tid;
        const int head = d0 >> 6;
        const int dh0  = d0 & 63;
        *(float4*)(dst + ((size_t)(b * H + head) * L + l) * DH + dh0) =
            make_float4(out[0], out[1], out[2], out[3]);
        __syncthreads();
    }

    {
        const float4 vv = *(const float4*)(g_qkv + (size_t)t * (3 * D) + 2 * D + 4 * tid);
        const int d0   = 4 * tid;
        const int head = d0 >> 6;
        const int dh0  = d0 & 63;
        *(float4*)(g_v + ((size_t)(b * H + head) * L + l) * DH + dh0) = vv;
    }
}

// ---------------------------------------------------------------------------
// Kernel 4: flash attention fp32 with FFMA2. grid = (L/64, B*H), 256 threads.
// ---------------------------------------------------------------------------
constexpr int ATTN_PAD   = 68;
constexpr int ATTN_SMEM_FLOATS = 4 * 64 * ATTN_PAD + 3 * 64;
constexpr size_t ATTN_SMEM_BYTES = ATTN_SMEM_FLOATS * sizeof(float);

__global__ void __launch_bounds__(256) attn_kernel(float* __restrict__ ctx)
{
    extern __shared__ float smem[];
    float* Qt   = smem;
    float* Kt   = Qt + 64 * ATTN_PAD;
    float* Vs   = Kt + 64 * ATTN_PAD;
    float* Ps   = Vs + 64 * ATTN_PAD;
    float* m_s  = Ps + 64 * ATTN_PAD;
    float* l_s  = m_s + 64;
    float* al_s = l_s + 64;

    const int tid = threadIdx.x;
    const int tx  = tid & 15;
    const int ty  = tid >> 4;
    const int bh  = blockIdx.y;
    const int b   = bh / H;
    const int h   = bh % H;
    const int q0  = blockIdx.x * 64;

    const int i0 = ty * 4;   // query-row fragment base
    const int c0 = tx * 4;   // key-col / headdim fragment base

    // Load Q tile transposed
    const float* Qbase = g_q + ((size_t)bh * L + q0) * DH;
    #pragma unroll
    for (int r = 0; r < 4; r++) {
        int idx  = tid + r * 256;          // 1024 float4 slots
        int row  = idx >> 4;               // 0..63
        int colb = (idx & 15) * 4;         // 0..60
        float4 qv = *(const float4*)(Qbase + row * DH + colb);
        Qt[(colb + 0) * ATTN_PAD + row] = qv.x;
        Qt[(colb + 1) * ATTN_PAD + row] = qv.y;
        Qt[(colb + 2) * ATTN_PAD + row] = qv.z;
        Qt[(colb + 3) * ATTN_PAD + row] = qv.w;
    }
    if (tid < 64) { m_s[tid] = -1e30f; l_s[tid] = 0.0f; }

    u64 o2[4][2];
    #pragma unroll
    for (int i = 0; i < 4; i++) { o2[i][0] = 0ull; o2[i][1] = 0ull; }

    __syncthreads();

    for (int kt = 0; kt < L / 64; kt++) {
        const float* Kbase = g_k + ((size_t)bh * L + kt * 64) * DH;
        const float* Vbase = g_v + ((size_t)bh * L + kt * 64) * DH;
        #pragma unroll
        for (int r = 0; r < 4; r++) {
            int idx  = tid + r * 256;
            int row  = idx >> 4;
            int colb = (idx & 15) * 4;
            float4 kv = *(const float4*)(Kbase + row * DH + colb);
            Kt[(colb + 0) * ATTN_PAD + row] = kv.x;
            Kt[(colb + 1) * ATTN_PAD + row] = kv.y;
            Kt[(colb + 2) * ATTN_PAD + row] = kv.z;
            Kt[(colb + 3) * ATTN_PAD + row] = kv.w;
            *(float4*)&Vs[row * ATTN_PAD + colb] = *(const float4*)(Vbase + row * DH + colb);
        }
        __syncthreads();

        // S = Q K^T  (thread: rows i0..i0+3, cols c0..c0+3), FFMA2
        u64 s2[4][2];
        #pragma unroll
        for (int i = 0; i < 4; i++) { s2[i][0] = 0ull; s2[i][1] = 0ull; }

        #pragma unroll 8
        for (int d = 0; d < DH; d++) {
            float4 qf = *(const float4*)&Qt[d * ATTN_PAD + i0];
            ulonglong2 kf = *(const ulonglong2*)&Kt[d * ATTN_PAD + c0];
            float qa[4] = {qf.x, qf.y, qf.z, qf.w};
            #pragma unroll
            for (int i = 0; i < 4; i++) {
                u64 qd = f2_dup(qa[i]);
                s2[i][0] = f2_fma(qd, kf.x, s2[i][0]);
                s2[i][1] = f2_fma(qd, kf.y, s2[i][1]);
            }
        }
        #pragma unroll
        for (int i = 0; i < 4; i++) {
            float2 a = f2_unpack(s2[i][0]);
            float2 bb = f2_unpack(s2[i][1]);
            Ps[(c0 + 0) * ATTN_PAD + (i0 + i)] = a.x  * SCALE;
            Ps[(c0 + 1) * ATTN_PAD + (i0 + i)] = a.y  * SCALE;
            Ps[(c0 + 2) * ATTN_PAD + (i0 + i)] = bb.x * SCALE;
            Ps[(c0 + 3) * ATTN_PAD + (i0 + i)] = bb.y * SCALE;
        }
        __syncthreads();

        // Online softmax: 4 threads per query row (r = tid>>2, q = tid&3)
        {
            const int r = tid >> 2;
            const int q = tid & 3;
            const float mo = m_s[r];
            float mx = mo;
            #pragma unroll
            for (int jj = 0; jj < 16; jj++)
                mx = fmaxf(mx, Ps[(q * 16 + jj) * ATTN_PAD + r]);
            mx = fmaxf(mx, __shfl_xor_sync(0xffffffffu, mx, 1));
            mx = fmaxf(mx, __shfl_xor_sync(0xffffffffu, mx, 2));
            float sum = 0.0f;
            #pragma unroll
            for (int jj = 0; jj < 16; jj++) {
                float* p = &Ps[(q * 16 + jj) * ATTN_PAD + r];
                float e = __expf(*p - mx);
                *p = e;
                sum += e;
            }
            sum += __shfl_xor_sync(0xffffffffu, sum, 1);
            sum += __shfl_xor_sync(0xffffffffu, sum, 2);
            if (q == 0) {
                float al = __expf(mo - mx);
                m_s[r]  = mx;
                l_s[r]  = l_s[r] * al + sum;
                al_s[r] = al;
            }
        }
        __syncthreads();

        // Rescale accumulators, then O += P @ V (FFMA2)
        #pragma unroll
        for (int i = 0; i < 4; i++) {
            u64 al2 = f2_dup(al_s[i0 + i]);
            o2[i][0] = f2_mul(o2[i][0], al2);
            o2[i][1] = f2_mul(o2[i][1], al2);
        }

        #pragma unroll 8
        for (int j = 0; j < 64; j++) {
            float4 pf = *(const float4*)&Ps[j * ATTN_PAD + i0];
            ulonglong2 vf = *(const ulonglong2*)&Vs[j * ATTN_PAD + c0];
            float pa[4] = {pf.x, pf.y, pf.z, pf.w};
            #pragma unroll
            for (int i = 0; i < 4; i++) {
                u64 pd = f2_dup(pa[i]);
                o2[i][0] = f2_fma(pd, vf.x, o2[i][0]);
                o2[i][1] = f2_fma(pd, vf.y, o2[i][1]);
            }
        }
        __syncthreads();
    }

    // Epilogue: normalize and write ctx[b, l, h*64 + c]
    #pragma unroll
    for (int i = 0; i < 4; i++) {
        const float inv = 1.0f / l_s[i0 + i];
        const int   lq  = q0 + i0 + i;
        float2 a = f2_unpack(o2[i][0]);
        float2 bb = f2_unpack(o2[i][1]);
        *(float4*)(ctx + ((size_t)(b * L + lq) * D) + h * DH + c0) =
            make_float4(a.x * inv, a.y * inv, bb.x * inv, bb.y * inv);
    }
}

// ---------------------------------------------------------------------------
// Launch
// ---------------------------------------------------------------------------
extern "C" void kernel_launch(void* const* d_in, const int* in_sizes, int n_in,
                              void* d_out, int out_size)
{
    const float* x      = (const float*)d_in[0];
    const float* ln_w   = (const float*)d_in[1];
    const float* ln_b   = (const float*)d_in[2];
    const float* w_qkv  = (const float*)d_in[3];
    const float* q_ln_w = (const float*)d_in[4];
    const float* k_ln_w = (const float*)d_in[5];
    const float* w_out  = (const float*)d_in[6];
    float* out = (float*)d_out;

    float *h, *qkv, *ctx;
    cudaGetSymbolAddress((void**)&h,   g_h);
    cudaGetSymbolAddress((void**)&qkv, g_qkv);
    cudaGetSymbolAddress((void**)&ctx, g_ctx);

    cudaFuncSetAttribute(attn_kernel, cudaFuncAttributeMaxDynamicSharedMemorySize,
                         (int)ATTN_SMEM_BYTES);

    // 1. LN(x) -> g_h
    ln_kernel<<<BL, 256>>>(x, ln_w, ln_b);

    // 2. qkv = h @ w_qkv^T   [4096, 3072]
    {
        dim3 grid(3 * D / GBN, BL / GBM);
        gemm_nt_kernel<<<grid, 256>>>(h, w_qkv, qkv, BL, 3 * D, D);
    }

    // 3. q/k LN + RoPE + transpose, v transpose
    qk_rope_kernel<<<BL, 256>>>(q_ln_w, k_ln_w);

    // 4. attention -> g_ctx  [B,L,H*DH]
    {
        dim3 grid(L / 64, B * H);
        attn_kernel<<<grid, 256, ATTN_SMEM_BYTES>>>(ctx);
    }

    // 5. out = ctx @ w_out^T  [4096, 1024]
    {
        dim3 grid(D / GBN, BL / GBM);
        gemm_nt_kernel<<<grid, 256>>>(ctx, w_out, out, BL, D, D);
    }
}

// round 3
// speedup vs baseline: 2.6415x; 2.6415x over previous
#include <cuda_runtime.h>
#include <math.h>
#include <stdint.h>

// Problem constants
constexpr int B  = 2;
constexpr int L  = 2048;
constexpr int D  = 1024;
constexpr int H  = 16;
constexpr int DH = 64;
constexpr int BL = B * L;          // 4096 tokens
constexpr float EPS   = 1e-5f;
constexpr float SCALE = 0.125f;    // 1/sqrt(64)
constexpr float LOG_ROPE_BASE = 9.210340371976184f; // ln(10000)

// ---------------------------------------------------------------------------
// Scratch
// ---------------------------------------------------------------------------
__device__ float g_h[BL * D];            // post-LN hidden
__device__ float g_qkv[BL * 3 * D];      // qkv projection
__device__ float g_q[BL * D];            // q  [B,H,L,DH], tf32-rounded
__device__ float g_k[BL * D];            // k  [B,H,L,DH], tf32-rounded
__device__ float g_v[BL * D];            // v  [B,H,L,DH], tf32-rounded
__device__ float g_ctx[BL * D];          // attention output [B,L,H*DH]

// ---------------------------------------------------------------------------
// tf32 helpers
// ---------------------------------------------------------------------------
__device__ __forceinline__ float tf32r(float f) {
    uint32_t u; asm("cvt.rna.tf32.f32 %0, %1;" : "=r"(u) : "f"(f));
    return __uint_as_float(u);
}

// mma.sync m16n8k8 tf32, D = A*B + D
__device__ __forceinline__ void mma8(float* c, const uint32_t* a, const uint32_t* b) {
    asm volatile(
        "mma.sync.aligned.m16n8k8.row.col.f32.tf32.tf32.f32 "
        "{%0,%1,%2,%3},{%4,%5,%6,%7},{%8,%9},{%0,%1,%2,%3};"
        : "+f"(c[0]), "+f"(c[1]), "+f"(c[2]), "+f"(c[3])
        : "r"(a[0]), "r"(a[1]), "r"(a[2]), "r"(a[3]), "r"(b[0]), "r"(b[1]));
}

// ---------------------------------------------------------------------------
// Block reduction (256 threads)
// ---------------------------------------------------------------------------
__device__ __forceinline__ float block_reduce_sum_256(float v, float* sbuf) {
    int tid = threadIdx.x;
    #pragma unroll
    for (int o = 16; o > 0; o >>= 1) v += __shfl_xor_sync(0xffffffffu, v, o);
    if ((tid & 31) == 0) sbuf[tid >> 5] = v;
    __syncthreads();
    if (tid < 8) {
        float w = sbuf[tid];
        #pragma unroll
        for (int o = 4; o > 0; o >>= 1) w += __shfl_xor_sync(0xffu, w, o);
        if (tid == 0) sbuf[0] = w;
    }
    __syncthreads();
    float r = sbuf[0];
    __syncthreads();
    return r;
}

// ---------------------------------------------------------------------------
// Kernel 1: LayerNorm over D=1024, one block (256 thr) per token.
// ---------------------------------------------------------------------------
__global__ void __launch_bounds__(256) ln_kernel(
    const float* __restrict__ x,
    const float* __restrict__ w,
    const float* __restrict__ bias)
{
    __shared__ float sbuf[8];
    const int t   = blockIdx.x;
    const int tid = threadIdx.x;

    const float4 xv = *(const float4*)(x + (size_t)t * D + 4 * tid);
    float s  = xv.x + xv.y + xv.z + xv.w;
    float ss = fmaf(xv.x, xv.x, fmaf(xv.y, xv.y, fmaf(xv.z, xv.z, xv.w * xv.w)));
    s  = block_reduce_sum_256(s,  sbuf);
    ss = block_reduce_sum_256(ss, sbuf);

    const float mu = s * (1.0f / D);
    const float rs = rsqrtf(ss * (1.0f / D) - mu * mu + EPS);

    const float4 wv = *(const float4*)(w    + 4 * tid);
    const float4 bv = *(const float4*)(bias + 4 * tid);
    float4 ov;
    ov.x = (xv.x - mu) * rs * wv.x + bv.x;
    ov.y = (xv.y - mu) * rs * wv.y + bv.y;
    ov.z = (xv.z - mu) * rs * wv.z + bv.z;
    ov.w = (xv.w - mu) * rs * wv.w + bv.w;
    *(float4*)(g_h + (size_t)t * D + 4 * tid) = ov;
}

// ---------------------------------------------------------------------------
// Kernel 2/5: tf32 tensor-core GEMM-NT  C[m,n] = sum_k A[m,k]*Bm[n,k]
// 128x128x16 block tile, 8 warps (2x4), warp tile 64x32, mma.m16n8k8.
// smem layout [row][k] with stride 20 (≡4 mod 32 -> conflict-free frags).
// ---------------------------------------------------------------------------
constexpr int GSK = 20;

__global__ void __launch_bounds__(256) gemm_nt_tf32(
    const float* __restrict__ A,
    const float* __restrict__ Bm,
    float* __restrict__ C,
    int M, int N, int K)
{
    __shared__ float As[128][GSK];
    __shared__ float Bs[128][GSK];

    const int tid  = threadIdx.x;
    const int lane = tid & 31;
    const int g    = lane >> 2;      // 0..7
    const int tg   = lane & 3;       // 0..3
    const int wid  = tid >> 5;
    const int wm   = wid >> 2;       // 0..1 -> m offset 64*wm
    const int wn   = wid & 3;        // 0..3 -> n offset 32*wn
    const int m0   = blockIdx.y * 128;
    const int n0   = blockIdx.x * 128;

    const int lr = tid >> 2;         // 0..63
    const int lc = (tid & 3) * 4;    // 0,4,8,12

    float acc[4][4][4];
    #pragma unroll
    for (int mt = 0; mt < 4; mt++)
        #pragma unroll
        for (int nt = 0; nt < 4; nt++)
            #pragma unroll
            for (int i = 0; i < 4; i++) acc[mt][nt][i] = 0.0f;

    // prefetch first tile
    float4 pa0 = *(const float4*)(A  + (size_t)(m0 + lr)      * K + lc);
    float4 pa1 = *(const float4*)(A  + (size_t)(m0 + lr + 64) * K + lc);
    float4 pb0 = *(const float4*)(Bm + (size_t)(n0 + lr)      * K + lc);
    float4 pb1 = *(const float4*)(Bm + (size_t)(n0 + lr + 64) * K + lc);

    for (int k0 = 0; k0 < K; k0 += 16) {
        *(float4*)&As[lr][lc]      = make_float4(tf32r(pa0.x), tf32r(pa0.y), tf32r(pa0.z), tf32r(pa0.w));
        *(float4*)&As[lr + 64][lc] = make_float4(tf32r(pa1.x), tf32r(pa1.y), tf32r(pa1.z), tf32r(pa1.w));
        *(float4*)&Bs[lr][lc]      = make_float4(tf32r(pb0.x), tf32r(pb0.y), tf32r(pb0.z), tf32r(pb0.w));
        *(float4*)&Bs[lr + 64][lc] = make_float4(tf32r(pb1.x), tf32r(pb1.y), tf32r(pb1.z), tf32r(pb1.w));
        __syncthreads();

        if (k0 + 16 < K) {
            pa0 = *(const float4*)(A  + (size_t)(m0 + lr)      * K + k0 + 16 + lc);
            pa1 = *(const float4*)(A  + (size_t)(m0 + lr + 64) * K + k0 + 16 + lc);
            pb0 = *(const float4*)(Bm + (size_t)(n0 + lr)      * K + k0 + 16 + lc);
            pb1 = *(const float4*)(Bm + (size_t)(n0 + lr + 64) * K + k0 + 16 + lc);
        }

        #pragma unroll
        for (int ks = 0; ks < 16; ks += 8) {
            uint32_t a[4][4], b[4][2];
            #pragma unroll
            for (int mt = 0; mt < 4; mt++) {
                const int m = wm * 64 + mt * 16 + g;
                a[mt][0] = __float_as_uint(As[m][ks + tg]);
                a[mt][1] = __float_as_uint(As[m + 8][ks + tg]);
                a[mt][2] = __float_as_uint(As[m][ks + tg + 4]);
                a[mt][3] = __float_as_uint(As[m + 8][ks + tg + 4]);
            }
            #pragma unroll
            for (int nt = 0; nt < 4; nt++) {
                const int n = wn * 32 + nt * 8 + g;
                b[nt][0] = __float_as_uint(Bs[n][ks + tg]);
                b[nt][1] = __float_as_uint(Bs[n][ks + tg + 4]);
            }
            #pragma unroll
            for (int mt = 0; mt < 4; mt++)
                #pragma unroll
                for (int nt = 0; nt < 4; nt++)
                    mma8(acc[mt][nt], a[mt], b[nt]);
        }
        __syncthreads();
    }

    #pragma unroll
    for (int mt = 0; mt < 4; mt++) {
        const int m = m0 + wm * 64 + mt * 16 + g;
        #pragma unroll
        for (int nt = 0; nt < 4; nt++) {
            const int n = n0 + wn * 32 + nt * 8 + 2 * tg;
            *(float2*)(C + (size_t)m * N + n)       = make_float2(acc[mt][nt][0], acc[mt][nt][1]);
            *(float2*)(C + (size_t)(m + 8) * N + n) = make_float2(acc[mt][nt][2], acc[mt][nt][3]);
        }
    }
}

// ---------------------------------------------------------------------------
// Kernel 3: per-token weight-only LN on q/k + RoPE + transpose into [B,H,L,DH]
// Outputs tf32-rounded (consumed only by tensor-core attention).
// ---------------------------------------------------------------------------
__global__ void __launch_bounds__(256) qk_rope_kernel(
    const float* __restrict__ q_ln_w,
    const float* __restrict__ k_ln_w)
{
    __shared__ float sm[D];
    __shared__ float sbuf[8];

    const int t   = blockIdx.x;
    const int tid = threadIdx.x;
    const int b   = t / L;
    const int l   = t % L;

    #pragma unroll
    for (int seg = 0; seg < 2; seg++) {
        const float* base = g_qkv + (size_t)t * (3 * D) + seg * D;
        const float* w    = (seg == 0) ? q_ln_w : k_ln_w;
        float*       dst  = (seg == 0) ? g_q    : g_k;

        const float4 xv = *(const float4*)(base + 4 * tid);
        float s  = xv.x + xv.y + xv.z + xv.w;
        float ss = fmaf(xv.x, xv.x, fmaf(xv.y, xv.y, fmaf(xv.z, xv.z, xv.w * xv.w)));
        s  = block_reduce_sum_256(s,  sbuf);
        ss = block_reduce_sum_256(ss, sbuf);
        const float mu = s * (1.0f / D);
        const float rs = rsqrtf(ss * (1.0f / D) - mu * mu + EPS);

        const float4 wv = *(const float4*)(w + 4 * tid);
        sm[4 * tid + 0] = (xv.x - mu) * rs * wv.x;
        sm[4 * tid + 1] = (xv.y - mu) * rs * wv.y;
        sm[4 * tid + 2] = (xv.z - mu) * rs * wv.z;
        sm[4 * tid + 3] = (xv.w - mu) * rs * wv.w;
        __syncthreads();

        float out[4];
        #pragma unroll
        for (int c = 0; c < 4; c++) {
            int d  = 4 * tid + c;
            int dh = d & 63;
            int i  = dh & 31;
            float inv_freq = expf(-(float)(2 * i) * (1.0f / 64.0f) * LOG_ROPE_BASE);
            float freq = (float)l * inv_freq;
            float sn, cs;
            sincosf(freq, &sn, &cs);
            if (dh < 32) out[c] = sm[d] * cs - sm[d + 32] * sn;
            else         out[c] = sm[d] * cs + sm[d - 32] * sn;
        }
        const int d0   = 4 * tid;
        const int head = d0 >> 6;
        const int dh0  = d0 & 63;
        *(float4*)(dst + ((size_t)(b * H + head) * L + l) * DH + dh0) =
            make_float4(tf32r(out[0]), tf32r(out[1]), tf32r(out[2]), tf32r(out[3]));
        __syncthreads();
    }

    {
        const float4 vv = *(const float4*)(g_qkv + (size_t)t * (3 * D) + 2 * D + 4 * tid);
        const int d0   = 4 * tid;
        const int head = d0 >> 6;
        const int dh0  = d0 & 63;
        *(float4*)(g_v + ((size_t)(b * H + head) * L + l) * DH + dh0) =
            make_float4(tf32r(vv.x), tf32r(vv.y), tf32r(vv.z), tf32r(vv.w));
    }
}

// ---------------------------------------------------------------------------
// Kernel 4: flash attention with tf32 mma. grid = (L/64, B*H), 256 thr.
// Warp layout: wm=wid&3 (16 q-rows each), wn=wid>>2 (32-col half).
// smem: Qs[64][68], Ks[64][68], Vs[64][72], Ps[64][68], m/l/al[64].
// ---------------------------------------------------------------------------
constexpr int SQ = 68;
constexpr int SV = 72;
constexpr int ATTN_SMEM_FLOATS = 3 * 64 * SQ + 64 * SV + 3 * 64;
constexpr size_t ATTN_SMEM_BYTES = ATTN_SMEM_FLOATS * sizeof(float);

__global__ void __launch_bounds__(256) attn_tf32(float* __restrict__ ctx)
{
    extern __shared__ float smem[];
    float* Qs   = smem;                 // [64][68]
    float* Ks   = Qs + 64 * SQ;         // [64][68]
    float* Vs   = Ks + 64 * SQ;         // [64][72]
    float* Ps   = Vs + 64 * SV;         // [64][68]
    float* m_s  = Ps + 64 * SQ;
    float* l_s  = m_s + 64;
    float* al_s = l_s + 64;

    const int tid  = threadIdx.x;
    const int lane = tid & 31;
    const int g    = lane >> 2;
    const int tg   = lane & 3;
    const int wid  = tid >> 5;
    const int wm   = wid & 3;           // q-row tile
    const int wn   = wid >> 2;          // col half
    const int bh   = blockIdx.y;
    const int bb   = bh / H;
    const int hh   = bh % H;
    const int q0   = blockIdx.x * 64;
    const int qm   = wm * 16 + g;

    // Load Q tile (row-major, already tf32-rounded in gmem)
    const float* Qg = g_q + ((size_t)bh * L + q0) * DH;
    #pragma unroll
    for (int r = 0; r < 4; r++) {
        int idx  = tid + r * 256;
        int row  = idx >> 4;
        int colb = (idx & 15) * 4;
        *(float4*)&Qs[row * SQ + colb] = *(const float4*)(Qg + row * DH + colb);
    }
    if (tid < 64) { m_s[tid] = -1e30f; l_s[tid] = 0.0f; }
    __syncthreads();

    // Hoist Q fragments for all 8 k-steps
    uint32_t qa[8][4];
    #pragma unroll
    for (int ks = 0; ks < 8; ks++) {
        qa[ks][0] = __float_as_uint(Qs[qm * SQ + ks * 8 + tg]);
        qa[ks][1] = __float_as_uint(Qs[(qm + 8) * SQ + ks * 8 + tg]);
        qa[ks][2] = __float_as_uint(Qs[qm * SQ + ks * 8 + tg + 4]);
        qa[ks][3] = __float_as_uint(Qs[(qm + 8) * SQ + ks * 8 + tg + 4]);
    }

    float o[4][4];
    #pragma unroll
    for (int nt = 0; nt < 4; nt++)
        #pragma unroll
        for (int i = 0; i < 4; i++) o[nt][i] = 0.0f;

    for (int kt = 0; kt < L / 64; kt++) {
        const float* Kg = g_k + ((size_t)bh * L + kt * 64) * DH;
        const float* Vg = g_v + ((size_t)bh * L + kt * 64) * DH;
        #pragma unroll
        for (int r = 0; r < 4; r++) {
            int idx  = tid + r * 256;
            int row  = idx >> 4;
            int colb = (idx & 15) * 4;
            *(float4*)&Ks[row * SQ + colb] = *(const float4*)(Kg + row * DH + colb);
            *(float4*)&Vs[row * SV + colb] = *(const float4*)(Vg + row * DH + colb);
        }
        __syncthreads();

        // S = Q K^T over dh (8 k-steps)
        float s[4][4];
        #pragma unroll
        for (int nt = 0; nt < 4; nt++)
            #pragma unroll
            for (int i = 0; i < 4; i++) s[nt][i] = 0.0f;

        #pragma unroll
        for (int ks = 0; ks < 8; ks++) {
            uint32_t bfr[4][2];
            #pragma unroll
            for (int nt = 0; nt < 4; nt++) {
                const int kn = wn * 32 + nt * 8 + g;
                bfr[nt][0] = __float_as_uint(Ks[kn * SQ + ks * 8 + tg]);
                bfr[nt][1] = __float_as_uint(Ks[kn * SQ + ks * 8 + tg + 4]);
            }
            #pragma unroll
            for (int nt = 0; nt < 4; nt++) mma8(s[nt], qa[ks], bfr[nt]);
        }
        // store scaled S -> Ps (row-major [q][key])
        #pragma unroll
        for (int nt = 0; nt < 4; nt++) {
            const int col = wn * 32 + nt * 8 + 2 * tg;
            *(float2*)&Ps[qm * SQ + col]       = make_float2(s[nt][0] * SCALE, s[nt][1] * SCALE);
            *(float2*)&Ps[(qm + 8) * SQ + col] = make_float2(s[nt][2] * SCALE, s[nt][3] * SCALE);
        }
        __syncthreads();

        // Online softmax: 4 threads per row
        {
            const int r  = tid >> 2;
            const int qq = tid & 3;
            const float mo = m_s[r];
            float mx = mo;
            float4 pv[4];
            #pragma unroll
            for (int j = 0; j < 4; j++) {
                pv[j] = *(const float4*)&Ps[r * SQ + qq * 16 + j * 4];
                mx = fmaxf(mx, fmaxf(fmaxf(pv[j].x, pv[j].y), fmaxf(pv[j].z, pv[j].w)));
            }
            mx = fmaxf(mx, __shfl_xor_sync(0xffffffffu, mx, 1));
            mx = fmaxf(mx, __shfl_xor_sync(0xffffffffu, mx, 2));
            float sum = 0.0f;
            #pragma unroll
            for (int j = 0; j < 4; j++) {
                float4 e;
                e.x = tf32r(__expf(pv[j].x - mx));
                e.y = tf32r(__expf(pv[j].y - mx));
                e.z = tf32r(__expf(pv[j].z - mx));
                e.w = tf32r(__expf(pv[j].w - mx));
                sum += (e.x + e.y) + (e.z + e.w);
                *(float4*)&Ps[r * SQ + qq * 16 + j * 4] = e;
            }
            sum += __shfl_xor_sync(0xffffffffu, sum, 1);
            sum += __shfl_xor_sync(0xffffffffu, sum, 2);
            if (qq == 0) {
                float al = __expf(mo - mx);
                m_s[r]  = mx;
                l_s[r]  = l_s[r] * al + sum;
                al_s[r] = al;
            }
        }
        __syncthreads();

        // Rescale O, then O += P @ V (8 k-steps over keys)
        {
            const float al0 = al_s[qm];
            const float al1 = al_s[qm + 8];
            #pragma unroll
            for (int nt = 0; nt < 4; nt++) {
                o[nt][0] *= al0; o[nt][1] *= al0;
                o[nt][2] *= al1; o[nt][3] *= al1;
            }
        }
        #pragma unroll
        for (int ks = 0; ks < 8; ks++) {
            uint32_t a[4];
            a[0] = __float_as_uint(Ps[qm * SQ + ks * 8 + tg]);
            a[1] = __float_as_uint(Ps[(qm + 8) * SQ + ks * 8 + tg]);
            a[2] = __float_as_uint(Ps[qm * SQ + ks * 8 + tg + 4]);
            a[3] = __float_as_uint(Ps[(qm + 8) * SQ + ks * 8 + tg + 4]);
            #pragma unroll
            for (int nt = 0; nt < 4; nt++) {
                const int dn = wn * 32 + nt * 8 + g;
                uint32_t bf[2];
                bf[0] = __float_as_uint(Vs[(ks * 8 + tg) * SV + dn]);
                bf[1] = __float_as_uint(Vs[(ks * 8 + tg + 4) * SV + dn]);
                mma8(o[nt], a, bf);
            }
        }
        __syncthreads();
    }

    // Epilogue
    const float inv0 = 1.0f / l_s[qm];
    const float inv1 = 1.0f / l_s[qm + 8];
    const int lq0 = q0 + qm;
    const int lq1 = q0 + qm + 8;
    #pragma unroll
    for (int nt = 0; nt < 4; nt++) {
        const int col = hh * 64 + wn * 32 + nt * 8 + 2 * tg;
        *(float2*)(ctx + (size_t)(bb * L + lq0) * D + col) =
            make_float2(o[nt][0] * inv0, o[nt][1] * inv0);
        *(float2*)(ctx + (size_t)(bb * L + lq1) * D + col) =
            make_float2(o[nt][2] * inv1, o[nt][3] * inv1);
    }
}

// ---------------------------------------------------------------------------
// Launch
// ---------------------------------------------------------------------------
extern "C" void kernel_launch(void* const* d_in, const int* in_sizes, int n_in,
                              void* d_out, int out_size)
{
    const float* x      = (const float*)d_in[0];
    const float* ln_w   = (const float*)d_in[1];
    const float* ln_b   = (const float*)d_in[2];
    const float* w_qkv  = (const float*)d_in[3];
    const float* q_ln_w = (const float*)d_in[4];
    const float* k_ln_w = (const float*)d_in[5];
    const float* w_out  = (const float*)d_in[6];
    float* out = (float*)d_out;

    float *h, *qkv, *ctx;
    cudaGetSymbolAddress((void**)&h,   g_h);
    cudaGetSymbolAddress((void**)&qkv, g_qkv);
    cudaGetSymbolAddress((void**)&ctx, g_ctx);

    cudaFuncSetAttribute(attn_tf32, cudaFuncAttributeMaxDynamicSharedMemorySize,
                         (int)ATTN_SMEM_BYTES);

    // 1. LN(x) -> g_h
    ln_kernel<<<BL, 256>>>(x, ln_w, ln_b);

    // 2. qkv = h @ w_qkv^T   [4096, 3072]
    {
        dim3 grid(3 * D / 128, BL / 128);
        gemm_nt_tf32<<<grid, 256>>>(h, w_qkv, qkv, BL, 3 * D, D);
    }

    // 3. q/k LN + RoPE + transpose (tf32-rounded), v transpose
    qk_rope_kernel<<<BL, 256>>>(q_ln_w, k_ln_w);

    // 4. attention -> g_ctx  [B,L,H*DH]
    {
        dim3 grid(L / 64, B * H);
        attn_tf32<<<grid, 256, ATTN_SMEM_BYTES>>>(ctx);
    }

    // 5. out = ctx @ w_out^T  [4096, 1024]
    {
        dim3 grid(D / 128, BL / 128);
        gemm_nt_tf32<<<grid, 256>>>(ctx, w_out, out, BL, D, D);
    }
}

// round 4
// speedup vs baseline: 3.0879x; 1.1690x over previous
#include <cuda_runtime.h>
#include <math.h>
#include <stdint.h>

// Problem constants
constexpr int B  = 2;
constexpr int L  = 2048;
constexpr int D  = 1024;
constexpr int H  = 16;
constexpr int DH = 64;
constexpr int BL = B * L;          // 4096 tokens
constexpr float EPS   = 1e-5f;
constexpr float LOG_ROPE_BASE = 9.210340371976184f; // ln(10000)

// ---------------------------------------------------------------------------
// Scratch
// ---------------------------------------------------------------------------
__device__ float g_h[BL * D];            // post-LN hidden
__device__ float g_qkv[BL * 3 * D];      // qkv projection
__device__ float g_q[BL * D];            // q  [B,H,L,DH], tf32-rounded
__device__ float g_k[BL * D];            // k  [B,H,L,DH], tf32-rounded
__device__ float g_v[BL * D];            // v  [B,H,L,DH], tf32-rounded
__device__ float g_ctx[BL * D];          // attention output [B,L,H*DH]

// ---------------------------------------------------------------------------
// tf32 / mma / cp.async helpers
// ---------------------------------------------------------------------------
__device__ __forceinline__ float tf32r(float f) {
    uint32_t u; asm("cvt.rna.tf32.f32 %0, %1;" : "=r"(u) : "f"(f));
    return __uint_as_float(u);
}

__device__ __forceinline__ void mma8(float* c, const uint32_t* a, const uint32_t* b) {
    asm volatile(
        "mma.sync.aligned.m16n8k8.row.col.f32.tf32.tf32.f32 "
        "{%0,%1,%2,%3},{%4,%5,%6,%7},{%8,%9},{%0,%1,%2,%3};"
        : "+f"(c[0]), "+f"(c[1]), "+f"(c[2]), "+f"(c[3])
        : "r"(a[0]), "r"(a[1]), "r"(a[2]), "r"(a[3]), "r"(b[0]), "r"(b[1]));
}

__device__ __forceinline__ void cp_async16(uint32_t dst, const void* src) {
    asm volatile("cp.async.cg.shared.global [%0], [%1], 16;" :: "r"(dst), "l"(src));
}

// ---------------------------------------------------------------------------
// Block reduction (256 threads)
// ---------------------------------------------------------------------------
__device__ __forceinline__ float block_reduce_sum_256(float v, float* sbuf) {
    int tid = threadIdx.x;
    #pragma unroll
    for (int o = 16; o > 0; o >>= 1) v += __shfl_xor_sync(0xffffffffu, v, o);
    if ((tid & 31) == 0) sbuf[tid >> 5] = v;
    __syncthreads();
    if (tid < 8) {
        float w = sbuf[tid];
        #pragma unroll
        for (int o = 4; o > 0; o >>= 1) w += __shfl_xor_sync(0xffu, w, o);
        if (tid == 0) sbuf[0] = w;
    }
    __syncthreads();
    float r = sbuf[0];
    __syncthreads();
    return r;
}

// ---------------------------------------------------------------------------
// Kernel 1: LayerNorm over D=1024, one block (256 thr) per token.
// ---------------------------------------------------------------------------
__global__ void __launch_bounds__(256) ln_kernel(
    const float* __restrict__ x,
    const float* __restrict__ w,
    const float* __restrict__ bias)
{
    __shared__ float sbuf[8];
    const int t   = blockIdx.x;
    const int tid = threadIdx.x;

    const float4 xv = *(const float4*)(x + (size_t)t * D + 4 * tid);
    float s  = xv.x + xv.y + xv.z + xv.w;
    float ss = fmaf(xv.x, xv.x, fmaf(xv.y, xv.y, fmaf(xv.z, xv.z, xv.w * xv.w)));
    s  = block_reduce_sum_256(s,  sbuf);
    ss = block_reduce_sum_256(ss, sbuf);

    const float mu = s * (1.0f / D);
    const float rs = rsqrtf(ss * (1.0f / D) - mu * mu + EPS);

    const float4 wv = *(const float4*)(w    + 4 * tid);
    const float4 bv = *(const float4*)(bias + 4 * tid);
    float4 ov;
    ov.x = (xv.x - mu) * rs * wv.x + bv.x;
    ov.y = (xv.y - mu) * rs * wv.y + bv.y;
    ov.z = (xv.z - mu) * rs * wv.z + bv.z;
    ov.w = (xv.w - mu) * rs * wv.w + bv.w;
    *(float4*)(g_h + (size_t)t * D + 4 * tid) = ov;
}

// ---------------------------------------------------------------------------
// Kernel 2/5: tf32 tensor-core GEMM-NT (unchanged from R3)
// ---------------------------------------------------------------------------
constexpr int GSK = 20;

__global__ void __launch_bounds__(256) gemm_nt_tf32(
    const float* __restrict__ A,
    const float* __restrict__ Bm,
    float* __restrict__ C,
    int M, int N, int K)
{
    __shared__ float As[128][GSK];
    __shared__ float Bs[128][GSK];

    const int tid  = threadIdx.x;
    const int lane = tid & 31;
    const int g    = lane >> 2;
    const int tg   = lane & 3;
    const int wid  = tid >> 5;
    const int wm   = wid >> 2;
    const int wn   = wid & 3;
    const int m0   = blockIdx.y * 128;
    const int n0   = blockIdx.x * 128;

    const int lr = tid >> 2;
    const int lc = (tid & 3) * 4;

    float acc[4][4][4];
    #pragma unroll
    for (int mt = 0; mt < 4; mt++)
        #pragma unroll
        for (int nt = 0; nt < 4; nt++)
            #pragma unroll
            for (int i = 0; i < 4; i++) acc[mt][nt][i] = 0.0f;

    float4 pa0 = *(const float4*)(A  + (size_t)(m0 + lr)      * K + lc);
    float4 pa1 = *(const float4*)(A  + (size_t)(m0 + lr + 64) * K + lc);
    float4 pb0 = *(const float4*)(Bm + (size_t)(n0 + lr)      * K + lc);
    float4 pb1 = *(const float4*)(Bm + (size_t)(n0 + lr + 64) * K + lc);

    for (int k0 = 0; k0 < K; k0 += 16) {
        *(float4*)&As[lr][lc]      = make_float4(tf32r(pa0.x), tf32r(pa0.y), tf32r(pa0.z), tf32r(pa0.w));
        *(float4*)&As[lr + 64][lc] = make_float4(tf32r(pa1.x), tf32r(pa1.y), tf32r(pa1.z), tf32r(pa1.w));
        *(float4*)&Bs[lr][lc]      = make_float4(tf32r(pb0.x), tf32r(pb0.y), tf32r(pb0.z), tf32r(pb0.w));
        *(float4*)&Bs[lr + 64][lc] = make_float4(tf32r(pb1.x), tf32r(pb1.y), tf32r(pb1.z), tf32r(pb1.w));
        __syncthreads();

        if (k0 + 16 < K) {
            pa0 = *(const float4*)(A  + (size_t)(m0 + lr)      * K + k0 + 16 + lc);
            pa1 = *(const float4*)(A  + (size_t)(m0 + lr + 64) * K + k0 + 16 + lc);
            pb0 = *(const float4*)(Bm + (size_t)(n0 + lr)      * K + k0 + 16 + lc);
            pb1 = *(const float4*)(Bm + (size_t)(n0 + lr + 64) * K + k0 + 16 + lc);
        }

        #pragma unroll
        for (int ks = 0; ks < 16; ks += 8) {
            uint32_t a[4][4], b[4][2];
            #pragma unroll
            for (int mt = 0; mt < 4; mt++) {
                const int m = wm * 64 + mt * 16 + g;
                a[mt][0] = __float_as_uint(As[m][ks + tg]);
                a[mt][1] = __float_as_uint(As[m + 8][ks + tg]);
                a[mt][2] = __float_as_uint(As[m][ks + tg + 4]);
                a[mt][3] = __float_as_uint(As[m + 8][ks + tg + 4]);
            }
            #pragma unroll
            for (int nt = 0; nt < 4; nt++) {
                const int n = wn * 32 + nt * 8 + g;
                b[nt][0] = __float_as_uint(Bs[n][ks + tg]);
                b[nt][1] = __float_as_uint(Bs[n][ks + tg + 4]);
            }
            #pragma unroll
            for (int mt = 0; mt < 4; mt++)
                #pragma unroll
                for (int nt = 0; nt < 4; nt++)
                    mma8(acc[mt][nt], a[mt], b[nt]);
        }
        __syncthreads();
    }

    #pragma unroll
    for (int mt = 0; mt < 4; mt++) {
        const int m = m0 + wm * 64 + mt * 16 + g;
        #pragma unroll
        for (int nt = 0; nt < 4; nt++) {
            const int n = n0 + wn * 32 + nt * 8 + 2 * tg;
            *(float2*)(C + (size_t)m * N + n)       = make_float2(acc[mt][nt][0], acc[mt][nt][1]);
            *(float2*)(C + (size_t)(m + 8) * N + n) = make_float2(acc[mt][nt][2], acc[mt][nt][3]);
        }
    }
}

// ---------------------------------------------------------------------------
// Kernel 3: q/k LN + RoPE + transpose (tf32-rounded outputs)
// ---------------------------------------------------------------------------
__global__ void __launch_bounds__(256) qk_rope_kernel(
    const float* __restrict__ q_ln_w,
    const float* __restrict__ k_ln_w)
{
    __shared__ float sm[D];
    __shared__ float sbuf[8];

    const int t   = blockIdx.x;
    const int tid = threadIdx.x;
    const int b   = t / L;
    const int l   = t % L;

    #pragma unroll
    for (int seg = 0; seg < 2; seg++) {
        const float* base = g_qkv + (size_t)t * (3 * D) + seg * D;
        const float* w    = (seg == 0) ? q_ln_w : k_ln_w;
        float*       dst  = (seg == 0) ? g_q    : g_k;

        const float4 xv = *(const float4*)(base + 4 * tid);
        float s  = xv.x + xv.y + xv.z + xv.w;
        float ss = fmaf(xv.x, xv.x, fmaf(xv.y, xv.y, fmaf(xv.z, xv.z, xv.w * xv.w)));
        s  = block_reduce_sum_256(s,  sbuf);
        ss = block_reduce_sum_256(ss, sbuf);
        const float mu = s * (1.0f / D);
        const float rs = rsqrtf(ss * (1.0f / D) - mu * mu + EPS);

        const float4 wv = *(const float4*)(w + 4 * tid);
        sm[4 * tid + 0] = (xv.x - mu) * rs * wv.x;
        sm[4 * tid + 1] = (xv.y - mu) * rs * wv.y;
        sm[4 * tid + 2] = (xv.z - mu) * rs * wv.z;
        sm[4 * tid + 3] = (xv.w - mu) * rs * wv.w;
        __syncthreads();

        float out[4];
        #pragma unroll
        for (int c = 0; c < 4; c++) {
            int d  = 4 * tid + c;
            int dh = d & 63;
            int i  = dh & 31;
            float inv_freq = expf(-(float)(2 * i) * (1.0f / 64.0f) * LOG_ROPE_BASE);
            float freq = (float)l * inv_freq;
            float sn, cs;
            sincosf(freq, &sn, &cs);
            if (dh < 32) out[c] = sm[d] * cs - sm[d + 32] * sn;
            else         out[c] = sm[d] * cs + sm[d - 32] * sn;
        }
        const int d0   = 4 * tid;
        const int head = d0 >> 6;
        const int dh0  = d0 & 63;
        *(float4*)(dst + ((size_t)(b * H + head) * L + l) * DH + dh0) =
            make_float4(tf32r(out[0]), tf32r(out[1]), tf32r(out[2]), tf32r(out[3]));
        __syncthreads();
    }

    {
        const float4 vv = *(const float4*)(g_qkv + (size_t)t * (3 * D) + 2 * D + 4 * tid);
        const int d0   = 4 * tid;
        const int head = d0 >> 6;
        const int dh0  = d0 & 63;
        *(float4*)(g_v + ((size_t)(b * H + head) * L + l) * DH + dh0) =
            make_float4(tf32r(vv.x), tf32r(vv.y), tf32r(vv.z), tf32r(vv.w));
    }
}

// ---------------------------------------------------------------------------
// Kernel 4 (v2): flash attention, warp-owns-full-key-range design.
// grid = (L/128, B*H), 256 threads. Warp w handles q rows [q0+16w, +16),
// all 64 keys of each KV tile. Softmax fully in registers.
// smem: Ks[2][64][68], Vs[2][64][72], Pw[8][16][68] (per-warp P pad,
// also used to stage Q at startup). cp.async 2-stage pipeline for K/V.
// ---------------------------------------------------------------------------
constexpr int SKK = 68;   // Ks stride
constexpr int SVV = 72;   // Vs stride
constexpr int SPP = 68;   // Pw stride
constexpr int ATTN_SMEM_FLOATS = 2 * 64 * SKK + 2 * 64 * SVV + 8 * 16 * SPP;
constexpr size_t ATTN_SMEM_BYTES = ATTN_SMEM_FLOATS * sizeof(float);
constexpr int NKT = L / 64;   // 32 KV tiles

__global__ void __launch_bounds__(256) attn_tf32_v2(float* __restrict__ ctx)
{
    extern __shared__ float smem[];
    float* KsBuf = smem;                          // 2 x [64][68]
    float* VsBuf = smem + 2 * 64 * SKK;           // 2 x [64][72]
    float* PwAll = smem + 2 * 64 * SKK + 2 * 64 * SVV;  // 8 x [16][68]

    const int tid  = threadIdx.x;
    const int lane = tid & 31;
    const int g    = lane >> 2;
    const int tg   = lane & 3;
    const int w    = tid >> 5;
    const int bh   = blockIdx.y;
    const int bb   = bh / H;
    const int hh   = bh % H;
    const int q0   = blockIdx.x * 128;

    float* Pw = PwAll + w * 16 * SPP;
    const uint32_t ks_smem = (uint32_t)__cvta_generic_to_shared(KsBuf);
    const uint32_t vs_smem = (uint32_t)__cvta_generic_to_shared(VsBuf);

    const float* Kg0 = g_k + (size_t)bh * L * DH;
    const float* Vg0 = g_v + (size_t)bh * L * DH;

    // --- prefetch tile 0 (cp.async, buffer 0) ---
    {
        #pragma unroll
        for (int r = 0; r < 4; r++) {
            int idx  = tid + r * 256;
            int row  = idx >> 4;
            int colb = (idx & 15) * 4;
            cp_async16(ks_smem + (row * SKK + colb) * 4, Kg0 + row * DH + colb);
            cp_async16(vs_smem + (row * SVV + colb) * 4, Vg0 + row * DH + colb);
        }
        asm volatile("cp.async.commit_group;");
    }

    // --- stage this warp's Q tile into Pw, hoist fragments (scale folded) ---
    uint32_t qa[8][4];
    {
        const float* Qg = g_q + ((size_t)bh * L + q0 + w * 16) * DH;
        #pragma unroll
        for (int r = 0; r < 8; r++) {
            int idx  = lane + r * 32;          // 256 float4 slots
            int row  = idx >> 4;
            int colb = (idx & 15) * 4;
            *(float4*)&Pw[row * SPP + colb] = *(const float4*)(Qg + row * DH + colb);
        }
        __syncwarp();
        #pragma unroll
        for (int ks = 0; ks < 8; ks++) {
            qa[ks][0] = __float_as_uint(0.125f * Pw[g * SPP + ks * 8 + tg]);
            qa[ks][1] = __float_as_uint(0.125f * Pw[(g + 8) * SPP + ks * 8 + tg]);
            qa[ks][2] = __float_as_uint(0.125f * Pw[g * SPP + ks * 8 + tg + 4]);
            qa[ks][3] = __float_as_uint(0.125f * Pw[(g + 8) * SPP + ks * 8 + tg + 4]);
        }
        __syncwarp();
    }

    float m0 = -1e30f, m1 = -1e30f, l0 = 0.0f, l1 = 0.0f;
    float o[8][4];
    #pragma unroll
    for (int nt = 0; nt < 8; nt++)
        #pragma unroll
        for (int i = 0; i < 4; i++) o[nt][i] = 0.0f;

    for (int kt = 0; kt < NKT; kt++) {
        const int cur = kt & 1;

        // prefetch next tile into other buffer
        if (kt + 1 < NKT) {
            const float* Kg = Kg0 + (size_t)(kt + 1) * 64 * DH;
            const float* Vg = Vg0 + (size_t)(kt + 1) * 64 * DH;
            const uint32_t kd = ks_smem + (cur ^ 1) * 64 * SKK * 4;
            const uint32_t vd = vs_smem + (cur ^ 1) * 64 * SVV * 4;
            #pragma unroll
            for (int r = 0; r < 4; r++) {
                int idx  = tid + r * 256;
                int row  = idx >> 4;
                int colb = (idx & 15) * 4;
                cp_async16(kd + (row * SKK + colb) * 4, Kg + row * DH + colb);
                cp_async16(vd + (row * SVV + colb) * 4, Vg + row * DH + colb);
            }
        }
        asm volatile("cp.async.commit_group;");
        asm volatile("cp.async.wait_group 1;");
        __syncthreads();

        const float* Ks = KsBuf + cur * 64 * SKK;
        const float* Vs = VsBuf + cur * 64 * SVV;

        // ---- S = (Q*scale) K^T : 16 x 64 per warp ----
        float s[8][4];
        #pragma unroll
        for (int nt = 0; nt < 8; nt++)
            #pragma unroll
            for (int i = 0; i < 4; i++) s[nt][i] = 0.0f;

        #pragma unroll
        for (int ks = 0; ks < 8; ks++) {
            uint32_t bk[8][2];
            #pragma unroll
            for (int nt = 0; nt < 8; nt++) {
                const int kn = nt * 8 + g;
                bk[nt][0] = __float_as_uint(Ks[kn * SKK + ks * 8 + tg]);
                bk[nt][1] = __float_as_uint(Ks[kn * SKK + ks * 8 + tg + 4]);
            }
            #pragma unroll
            for (int nt = 0; nt < 8; nt++) mma8(s[nt], qa[ks], bk[nt]);
        }

        // ---- online softmax in registers (rows g and g+8) ----
        float mx0 = -1e30f, mx1 = -1e30f;
        #pragma unroll
        for (int nt = 0; nt < 8; nt++) {
            mx0 = fmaxf(mx0, fmaxf(s[nt][0], s[nt][1]));
            mx1 = fmaxf(mx1, fmaxf(s[nt][2], s[nt][3]));
        }
        mx0 = fmaxf(mx0, __shfl_xor_sync(0xffffffffu, mx0, 1));
        mx0 = fmaxf(mx0, __shfl_xor_sync(0xffffffffu, mx0, 2));
        mx1 = fmaxf(mx1, __shfl_xor_sync(0xffffffffu, mx1, 1));
        mx1 = fmaxf(mx1, __shfl_xor_sync(0xffffffffu, mx1, 2));
        const float nm0 = fmaxf(m0, mx0);
        const float nm1 = fmaxf(m1, mx1);

        float sum0 = 0.0f, sum1 = 0.0f;
        #pragma unroll
        for (int nt = 0; nt < 8; nt++) {
            s[nt][0] = tf32r(__expf(s[nt][0] - nm0));
            s[nt][1] = tf32r(__expf(s[nt][1] - nm0));
            s[nt][2] = tf32r(__expf(s[nt][2] - nm1));
            s[nt][3] = tf32r(__expf(s[nt][3] - nm1));
            sum0 += s[nt][0] + s[nt][1];
            sum1 += s[nt][2] + s[nt][3];
        }
        sum0 += __shfl_xor_sync(0xffffffffu, sum0, 1);
        sum0 += __shfl_xor_sync(0xffffffffu, sum0, 2);
        sum1 += __shfl_xor_sync(0xffffffffu, sum1, 1);
        sum1 += __shfl_xor_sync(0xffffffffu, sum1, 2);

        const float al0 = __expf(m0 - nm0);
        const float al1 = __expf(m1 - nm1);
        l0 = l0 * al0 + sum0;  m0 = nm0;
        l1 = l1 * al1 + sum1;  m1 = nm1;

        // ---- store P (warp-private), rescale O ----
        #pragma unroll
        for (int nt = 0; nt < 8; nt++) {
            *(float2*)&Pw[g * SPP + nt * 8 + 2 * tg]       = make_float2(s[nt][0], s[nt][1]);
            *(float2*)&Pw[(g + 8) * SPP + nt * 8 + 2 * tg] = make_float2(s[nt][2], s[nt][3]);
        }
        #pragma unroll
        for (int nt = 0; nt < 8; nt++) {
            o[nt][0] *= al0; o[nt][1] *= al0;
            o[nt][2] *= al1; o[nt][3] *= al1;
        }
        __syncwarp();

        // ---- O += P @ V ----
        #pragma unroll
        for (int ks = 0; ks < 8; ks++) {
            uint32_t a[4];
            a[0] = __float_as_uint(Pw[g * SPP + ks * 8 + tg]);
            a[1] = __float_as_uint(Pw[(g + 8) * SPP + ks * 8 + tg]);
            a[2] = __float_as_uint(Pw[g * SPP + ks * 8 + tg + 4]);
            a[3] = __float_as_uint(Pw[(g + 8) * SPP + ks * 8 + tg + 4]);
            #pragma unroll
            for (int nt = 0; nt < 8; nt++) {
                uint32_t bv[2];
                bv[0] = __float_as_uint(Vs[(ks * 8 + tg) * SVV + nt * 8 + g]);
                bv[1] = __float_as_uint(Vs[(ks * 8 + tg + 4) * SVV + nt * 8 + g]);
                mma8(o[nt], a, bv);
            }
        }
        __syncthreads();   // everyone done with cur buffers before reuse
    }

    // ---- epilogue ----
    const float inv0 = 1.0f / l0;
    const float inv1 = 1.0f / l1;
    const int row0 = q0 + w * 16 + g;
    const int row1 = row0 + 8;
    #pragma unroll
    for (int nt = 0; nt < 8; nt++) {
        const int col = hh * DH + nt * 8 + 2 * tg;
        *(float2*)(ctx + (size_t)(bb * L + row0) * D + col) =
            make_float2(o[nt][0] * inv0, o[nt][1] * inv0);
        *(float2*)(ctx + (size_t)(bb * L + row1) * D + col) =
            make_float2(o[nt][2] * inv1, o[nt][3] * inv1);
    }
}

// ---------------------------------------------------------------------------
// Launch
// ---------------------------------------------------------------------------
extern "C" void kernel_launch(void* const* d_in, const int* in_sizes, int n_in,
                              void* d_out, int out_size)
{
    const float* x      = (const float*)d_in[0];
    const float* ln_w   = (const float*)d_in[1];
    const float* ln_b   = (const float*)d_in[2];
    const float* w_qkv  = (const float*)d_in[3];
    const float* q_ln_w = (const float*)d_in[4];
    const float* k_ln_w = (const float*)d_in[5];
    const float* w_out  = (const float*)d_in[6];
    float* out = (float*)d_out;

    float *h, *qkv, *ctx;
    cudaGetSymbolAddress((void**)&h,   g_h);
    cudaGetSymbolAddress((void**)&qkv, g_qkv);
    cudaGetSymbolAddress((void**)&ctx, g_ctx);

    cudaFuncSetAttribute(attn_tf32_v2, cudaFuncAttributeMaxDynamicSharedMemorySize,
                         (int)ATTN_SMEM_BYTES);

    // 1. LN(x) -> g_h
    ln_kernel<<<BL, 256>>>(x, ln_w, ln_b);

    // 2. qkv = h @ w_qkv^T   [4096, 3072]
    {
        dim3 grid(3 * D / 128, BL / 128);
        gemm_nt_tf32<<<grid, 256>>>(h, w_qkv, qkv, BL, 3 * D, D);
    }

    // 3. q/k LN + RoPE + transpose (tf32-rounded), v transpose
    qk_rope_kernel<<<BL, 256>>>(q_ln_w, k_ln_w);

    // 4. attention -> g_ctx  [B,L,H*DH]
    {
        dim3 grid(L / 128, B * H);
        attn_tf32_v2<<<grid, 256, ATTN_SMEM_BYTES>>>(ctx);
    }

    // 5. out = ctx @ w_out^T  [4096, 1024]
    {
        dim3 grid(D / 128, BL / 128);
        gemm_nt_tf32<<<grid, 256>>>(ctx, w_out, out, BL, D, D);
    }
}